// round 1
// baseline (speedup 1.0000x reference)
#include <cuda_runtime.h>
#include <math.h>

// Problem constants
#define TT 4096          // tokens (4*1024)
#define EE 23            // experts
#define KK 3             // top-k
#define DD 1024          // in features
#define HH 768           // hidden
#define TILE 128
#define BK 8
#define ROWS_MAX (TT*KK + EE*TILE)      // 12288 + 2944 = 15232
#define MTILES_MAX (ROWS_MAX/TILE)      // 119
#define OUT_MAIN (TT*DD)                // 4194304

// ---------------- scratch (device globals; allocation-free) ----------------
__device__ float g_gate_w[TT*KK];
__device__ int   g_top_idx[TT*KK];
__device__ int   g_counts[EE];
__device__ float g_Psum[EE];
__device__ int   g_cursor[EE];
__device__ int   g_seg_start[EE];
__device__ int   g_tile_expert[MTILES_MAX];
__device__ int   g_tile_row0[MTILES_MAX];
__device__ int   g_row_token[ROWS_MAX];
__device__ int   g_pos_of[TT*KK];
__device__ float g_Hbuf[(size_t)ROWS_MAX*HH];
__device__ float g_Ybuf[(size_t)ROWS_MAX*DD];
__device__ float g_Sbuf[(size_t)TT*HH];

__device__ __forceinline__ float gelu_exact(float v) {
    return 0.5f * v * (1.0f + erff(v * 0.70710678118654752440f));
}

// ---------------- init ----------------
__global__ void init_kernel() {
    int idx = blockIdx.x * 256 + threadIdx.x;
    if (idx < ROWS_MAX) g_row_token[idx] = -1;
    if (idx < EE) { g_counts[idx] = 0; g_Psum[idx] = 0.0f; g_cursor[idx] = 0; }
}

// ---------------- gating: sigmoid gate, top-3, counts, P sums ----------------
__global__ void gate_kernel(const float* __restrict__ x,
                            const float* __restrict__ gW,
                            const float* __restrict__ gb,
                            const float* __restrict__ bias) {
    __shared__ float xs[DD];
    __shared__ float gate_raw[EE];
    int t = blockIdx.x;
    const float* xp = x + (size_t)t * DD;
    for (int i = threadIdx.x; i < DD; i += 256) xs[i] = xp[i];
    __syncthreads();

    int wid = threadIdx.x >> 5, lane = threadIdx.x & 31;
    for (int e = wid; e < EE; e += 8) {
        float s = 0.0f;
        for (int i = lane; i < DD; i += 32) s += xs[i] * gW[(size_t)i * EE + e];
        #pragma unroll
        for (int o = 16; o > 0; o >>= 1) s += __shfl_down_sync(0xffffffffu, s, o);
        if (lane == 0) gate_raw[e] = s + gb[e];
    }
    __syncthreads();

    if (threadIdx.x == 0) {
        float gsig[EE];
        float gsum = 0.0f;
        #pragma unroll
        for (int e = 0; e < EE; e++) {
            gsig[e] = 1.0f / (1.0f + expf(-gate_raw[e]));
            gsum += gsig[e];
        }
        // top-3 on gate + bias (strict > so earlier index wins ties, matching top_k)
        int i0 = -1, i1 = -1, i2 = -1;
        float v0 = -1e30f, v1 = -1e30f, v2 = -1e30f;
        #pragma unroll
        for (int e = 0; e < EE; e++) {
            float f = gsig[e] + bias[e];
            if (f > v0)      { v2 = v1; i2 = i1; v1 = v0; i1 = i0; v0 = f; i0 = e; }
            else if (f > v1) { v2 = v1; i2 = i1; v1 = f; i1 = e; }
            else if (f > v2) { v2 = f; i2 = e; }
        }
        float w0 = gsig[i0], w1 = gsig[i1], w2 = gsig[i2];
        float ws = w0 + w1 + w2;
        g_top_idx[t*KK+0] = i0; g_top_idx[t*KK+1] = i1; g_top_idx[t*KK+2] = i2;
        g_gate_w[t*KK+0] = w0 / ws; g_gate_w[t*KK+1] = w1 / ws; g_gate_w[t*KK+2] = w2 / ws;
        atomicAdd(&g_counts[i0], 1);
        atomicAdd(&g_counts[i1], 1);
        atomicAdd(&g_counts[i2], 1);
        float inv = 1.0f / gsum;
        #pragma unroll
        for (int e = 0; e < EE; e++) atomicAdd(&g_Psum[e], gsig[e] * inv);
    }
}

// ---------------- padded segment scan + tile map ----------------
__global__ void scan_kernel() {
    if (threadIdx.x == 0 && blockIdx.x == 0) {
        int row = 0, tile = 0;
        for (int e = 0; e < EE; e++) {
            g_seg_start[e] = row;
            int nt = (g_counts[e] + TILE - 1) / TILE;
            for (int j = 0; j < nt; j++) {
                g_tile_expert[tile] = e;
                g_tile_row0[tile] = row + j * TILE;
                tile++;
            }
            row += nt * TILE;
        }
        for (; tile < MTILES_MAX; tile++) g_tile_expert[tile] = -1;
    }
}

// ---------------- scatter tokens to expert rows ----------------
__global__ void scatter_kernel() {
    int t = blockIdx.x * 256 + threadIdx.x;
    if (t < TT) {
        #pragma unroll
        for (int k = 0; k < KK; k++) {
            int e = g_top_idx[t*KK + k];
            int p = atomicAdd(&g_cursor[e], 1);
            int row = g_seg_start[e] + p;
            g_row_token[row] = t;
            g_pos_of[t*KK + k] = row;
        }
    }
}

// ---------------- tiled SGEMM 128x128x8, 8x8 per thread ----------------
// ASEL: 0 = A param, 1 = g_Hbuf, 2 = g_Sbuf
// CSEL: 0 = C param, 1 = g_Hbuf, 2 = g_Ybuf, 3 = g_Sbuf
template<int ASEL, int CSEL, bool MOE, bool GATHER, bool GELU>
__global__ void __launch_bounds__(256, 2)
gemm_kernel(const float* __restrict__ Ap, const float* __restrict__ B,
            const float* __restrict__ biasB, float* __restrict__ Cp,
            int Kd, int Nd, long strideBexp) {
    const float* A = (ASEL == 0) ? Ap : (ASEL == 1 ? (const float*)g_Hbuf : (const float*)g_Sbuf);
    float* C = (CSEL == 0) ? Cp : (CSEL == 1 ? g_Hbuf : (CSEL == 2 ? g_Ybuf : g_Sbuf));

    int mt = blockIdx.x, nt = blockIdx.y;
    int expert = 0, row0;
    if (MOE) {
        expert = g_tile_expert[mt];
        if (expert < 0) return;
        row0 = g_tile_row0[mt];
    } else {
        row0 = mt * TILE;
    }
    const float* Bp = B + (MOE ? (size_t)expert * (size_t)strideBexp : (size_t)0);
    const float* bp = biasB + (MOE ? (size_t)expert * Nd : (size_t)0);
    int n0 = nt * TILE;

    __shared__ float As[BK][TILE];
    __shared__ float Bs[BK][TILE];
    __shared__ int   rtok[TILE];

    int tid = threadIdx.x;
    if (GATHER) {
        if (tid < TILE) rtok[tid] = g_row_token[row0 + tid];
        __syncthreads();
    }

    int arow = tid >> 1;           // 0..127
    int akq  = (tid & 1) * 4;      // 0 or 4
    int bk   = tid >> 5;           // 0..7
    int bn   = (tid & 31) * 4;     // 0..124
    int tx   = tid & 15;
    int ty   = tid >> 4;

    float acc[8][8];
    #pragma unroll
    for (int i = 0; i < 8; i++)
        #pragma unroll
        for (int j = 0; j < 8; j++) acc[i][j] = 0.0f;

    for (int k0 = 0; k0 < Kd; k0 += BK) {
        float4 av, bv;
        if (GATHER) {
            int tok = rtok[arow];
            av = (tok < 0) ? make_float4(0.f, 0.f, 0.f, 0.f)
                           : *(const float4*)&A[(size_t)tok * Kd + k0 + akq];
        } else {
            av = *(const float4*)&A[(size_t)(row0 + arow) * Kd + k0 + akq];
        }
        bv = *(const float4*)&Bp[(size_t)(k0 + bk) * Nd + n0 + bn];

        __syncthreads();
        As[akq + 0][arow] = av.x;
        As[akq + 1][arow] = av.y;
        As[akq + 2][arow] = av.z;
        As[akq + 3][arow] = av.w;
        *(float4*)&Bs[bk][bn] = bv;
        __syncthreads();

        #pragma unroll
        for (int kk = 0; kk < BK; kk++) {
            float4 a0 = *(float4*)&As[kk][ty * 8];
            float4 a1 = *(float4*)&As[kk][ty * 8 + 4];
            float4 b0 = *(float4*)&Bs[kk][tx * 8];
            float4 b1 = *(float4*)&Bs[kk][tx * 8 + 4];
            float ar[8] = {a0.x, a0.y, a0.z, a0.w, a1.x, a1.y, a1.z, a1.w};
            float br[8] = {b0.x, b0.y, b0.z, b0.w, b1.x, b1.y, b1.z, b1.w};
            #pragma unroll
            for (int i = 0; i < 8; i++)
                #pragma unroll
                for (int j = 0; j < 8; j++) acc[i][j] += ar[i] * br[j];
        }
    }

    #pragma unroll
    for (int i = 0; i < 8; i++) {
        int r = row0 + ty * 8 + i;
        float* cp = C + (size_t)r * Nd + n0 + tx * 8;
        float vals[8];
        #pragma unroll
        for (int j = 0; j < 8; j++) {
            float v = acc[i][j] + bp[n0 + tx * 8 + j];
            if (GELU) v = gelu_exact(v);
            vals[j] = v;
        }
        *(float4*)&cp[0] = make_float4(vals[0], vals[1], vals[2], vals[3]);
        *(float4*)&cp[4] = make_float4(vals[4], vals[5], vals[6], vals[7]);
    }
}

// ---------------- combine: out = shared + sum_k w * Y[pos] ----------------
__global__ void combine_kernel(float* __restrict__ out) {
    int t = blockIdx.x;
    int d = threadIdx.x * 4;
    float4 o = *(float4*)&out[(size_t)t * DD + d];
    #pragma unroll
    for (int k = 0; k < KK; k++) {
        int p = g_pos_of[t*KK + k];
        float w = g_gate_w[t*KK + k];
        float4 y = *(const float4*)&g_Ybuf[(size_t)p * DD + d];
        o.x += w * y.x; o.y += w * y.y; o.z += w * y.z; o.w += w * y.w;
    }
    *(float4*)&out[(size_t)t * DD + d] = o;
}

// ---------------- aux loss + counts ----------------
__global__ void finalize_kernel(float* __restrict__ extra, int write_counts) {
    if (threadIdx.x == 0) {
        float a = 0.0f;
        for (int e = 0; e < EE; e++) {
            float P = g_Psum[e] / (float)TT;
            float F = (float)EE * (float)g_counts[e] / (float)(KK * TT);
            a += P * F;
        }
        extra[0] = a;
    }
    if (write_counts && threadIdx.x < EE)
        extra[1 + threadIdx.x] = (float)g_counts[threadIdx.x];
}

extern "C" void kernel_launch(void* const* d_in, const int* in_sizes, int n_in,
                              void* d_out, int out_size) {
    const float* x    = (const float*)d_in[0];
    const float* gW   = (const float*)d_in[1];
    const float* gb   = (const float*)d_in[2];
    const float* bias = (const float*)d_in[3];
    const float* W1   = (const float*)d_in[4];
    const float* b1   = (const float*)d_in[5];
    const float* W2   = (const float*)d_in[6];
    const float* b2   = (const float*)d_in[7];
    const float* sW1  = (const float*)d_in[8];
    const float* sb1  = (const float*)d_in[9];
    const float* sW2  = (const float*)d_in[10];
    const float* sb2  = (const float*)d_in[11];
    float* out = (float*)d_out;

    init_kernel<<<(ROWS_MAX + 255) / 256, 256>>>();
    gate_kernel<<<TT, 256>>>(x, gW, gb, bias);
    scan_kernel<<<1, 32>>>();
    scatter_kernel<<<(TT + 255) / 256, 256>>>();

    // expert GEMM1: Hbuf = gelu(gather(x) @ W1_e + b1_e)   [rows x 768]
    gemm_kernel<0, 1, true, true, true>
        <<<dim3(MTILES_MAX, HH / TILE), 256>>>(x, W1, b1, nullptr, DD, HH, (long)DD * HH);
    // expert GEMM2: Ybuf = Hbuf @ W2_e + b2_e              [rows x 1024]
    gemm_kernel<1, 2, true, false, false>
        <<<dim3(MTILES_MAX, DD / TILE), 256>>>(nullptr, W2, b2, nullptr, HH, DD, (long)HH * DD);
    // shared GEMM1: Sbuf = gelu(x @ sW1 + sb1)             [4096 x 768]
    gemm_kernel<0, 3, false, false, true>
        <<<dim3(TT / TILE, HH / TILE), 256>>>(x, sW1, sb1, nullptr, DD, HH, 0);
    // shared GEMM2: out = Sbuf @ sW2 + sb2                 [4096 x 1024]
    gemm_kernel<2, 0, false, false, false>
        <<<dim3(TT / TILE, DD / TILE), 256>>>(nullptr, sW2, sb2, out, HH, DD, 0);

    combine_kernel<<<TT, 256>>>(out);

    if (out_size > OUT_MAIN) {
        int write_counts = (out_size >= OUT_MAIN + 1 + EE) ? 1 : 0;
        finalize_kernel<<<1, 32>>>(out + OUT_MAIN, write_counts);
    }
}

// round 2
// speedup vs baseline: 2.5735x; 2.5735x over previous
#include <cuda_runtime.h>
#include <math.h>
#include <stdint.h>

// Problem constants
#define TT 4096          // tokens
#define EE 23            // experts
#define KK 3             // top-k
#define DD 1024          // in features
#define HH 768           // hidden
#define TILE 128         // M tile
#define BN 256           // N tile
#define BKT 32           // K tile
#define ROWS_MAX (TT*KK + EE*TILE)      // 15232
#define MTILES_MAX (ROWS_MAX/TILE)      // 119
#define OUT_MAIN (TT*DD)

// smem layout (words): A stage 128*36 = 4608 ; B stage 32*264 = 8448
#define AW 4608
#define STAGEW (AW + 32*264)            // 13056 words
#define SMEM_BYTES (2 * STAGEW * 4)     // 104448

// ---------------- scratch (device globals; allocation-free) ----------------
__device__ float g_gate_w[TT*KK];
__device__ int   g_top_idx[TT*KK];
__device__ int   g_counts[EE];
__device__ float g_Psum[EE];
__device__ int   g_cursor[EE];
__device__ int   g_seg_start[EE];
__device__ int   g_tile_expert[MTILES_MAX];
__device__ int   g_tile_row0[MTILES_MAX];
__device__ int   g_row_token[ROWS_MAX];
__device__ int   g_pos_of[TT*KK];
__device__ float g_Hbuf[(size_t)ROWS_MAX*HH];
__device__ float g_Ybuf[(size_t)ROWS_MAX*DD];
__device__ float g_Sbuf[(size_t)TT*HH];
// tf32(rna)-rounded copies
__device__ float g_xc[(size_t)TT*DD];
__device__ float g_W1c[(size_t)EE*DD*HH];
__device__ float g_W2c[(size_t)EE*HH*DD];
__device__ float g_sW1c[(size_t)DD*HH];
__device__ float g_sW2c[(size_t)HH*DD];

__device__ __forceinline__ float gelu_exact(float v) {
    return 0.5f * v * (1.0f + erff(v * 0.70710678118654752440f));
}
__device__ __forceinline__ float tf32_rna(float v) {
    uint32_t r;
    asm("cvt.rna.tf32.f32 %0, %1;" : "=r"(r) : "f"(v));
    return __uint_as_float(r);
}

// ---------------- init ----------------
__global__ void init_kernel() {
    int idx = blockIdx.x * 256 + threadIdx.x;
    if (idx < ROWS_MAX) g_row_token[idx] = -1;
    if (idx < EE) { g_counts[idx] = 0; g_Psum[idx] = 0.0f; g_cursor[idx] = 0; }
}

// ---------------- tf32 rna convert ----------------
__global__ void convert_kernel(const float4* __restrict__ src, float4* __restrict__ dst, int n4) {
    int i = blockIdx.x * 256 + threadIdx.x;
    if (i < n4) {
        float4 v = src[i];
        v.x = tf32_rna(v.x); v.y = tf32_rna(v.y);
        v.z = tf32_rna(v.z); v.w = tf32_rna(v.w);
        dst[i] = v;
    }
}

// ---------------- gating ----------------
__global__ void gate_kernel(const float* __restrict__ x,
                            const float* __restrict__ gW,
                            const float* __restrict__ gb,
                            const float* __restrict__ bias) {
    __shared__ float xs[DD];
    __shared__ float gate_raw[EE];
    int t = blockIdx.x;
    const float* xp = x + (size_t)t * DD;
    for (int i = threadIdx.x; i < DD; i += 256) xs[i] = xp[i];
    __syncthreads();

    int wid = threadIdx.x >> 5, lane = threadIdx.x & 31;
    for (int e = wid; e < EE; e += 8) {
        float s = 0.0f;
        for (int i = lane; i < DD; i += 32) s += xs[i] * gW[(size_t)i * EE + e];
        #pragma unroll
        for (int o = 16; o > 0; o >>= 1) s += __shfl_down_sync(0xffffffffu, s, o);
        if (lane == 0) gate_raw[e] = s + gb[e];
    }
    __syncthreads();

    if (threadIdx.x == 0) {
        float gsig[EE];
        float gsum = 0.0f;
        #pragma unroll
        for (int e = 0; e < EE; e++) {
            gsig[e] = 1.0f / (1.0f + expf(-gate_raw[e]));
            gsum += gsig[e];
        }
        int i0 = -1, i1 = -1, i2 = -1;
        float v0 = -1e30f, v1 = -1e30f, v2 = -1e30f;
        #pragma unroll
        for (int e = 0; e < EE; e++) {
            float f = gsig[e] + bias[e];
            if (f > v0)      { v2 = v1; i2 = i1; v1 = v0; i1 = i0; v0 = f; i0 = e; }
            else if (f > v1) { v2 = v1; i2 = i1; v1 = f; i1 = e; }
            else if (f > v2) { v2 = f; i2 = e; }
        }
        float w0 = gsig[i0], w1 = gsig[i1], w2 = gsig[i2];
        float ws = w0 + w1 + w2;
        g_top_idx[t*KK+0] = i0; g_top_idx[t*KK+1] = i1; g_top_idx[t*KK+2] = i2;
        g_gate_w[t*KK+0] = w0 / ws; g_gate_w[t*KK+1] = w1 / ws; g_gate_w[t*KK+2] = w2 / ws;
        atomicAdd(&g_counts[i0], 1);
        atomicAdd(&g_counts[i1], 1);
        atomicAdd(&g_counts[i2], 1);
        float inv = 1.0f / gsum;
        #pragma unroll
        for (int e = 0; e < EE; e++) atomicAdd(&g_Psum[e], gsig[e] * inv);
    }
}

// ---------------- padded segment scan + tile map ----------------
__global__ void scan_kernel() {
    if (threadIdx.x == 0 && blockIdx.x == 0) {
        int row = 0, tile = 0;
        for (int e = 0; e < EE; e++) {
            g_seg_start[e] = row;
            int nt = (g_counts[e] + TILE - 1) / TILE;
            for (int j = 0; j < nt; j++) {
                g_tile_expert[tile] = e;
                g_tile_row0[tile] = row + j * TILE;
                tile++;
            }
            row += nt * TILE;
        }
        for (; tile < MTILES_MAX; tile++) g_tile_expert[tile] = -1;
    }
}

// ---------------- scatter ----------------
__global__ void scatter_kernel() {
    int t = blockIdx.x * 256 + threadIdx.x;
    if (t < TT) {
        #pragma unroll
        for (int k = 0; k < KK; k++) {
            int e = g_top_idx[t*KK + k];
            int p = atomicAdd(&g_cursor[e], 1);
            int row = g_seg_start[e] + p;
            g_row_token[row] = t;
            g_pos_of[t*KK + k] = row;
        }
    }
}

// ---------------- tf32 tensor-core GEMM ----------------
__device__ __forceinline__ void cpa16(uint32_t dst, const void* src, int srcbytes) {
    asm volatile("cp.async.cg.shared.global [%0], [%1], 16, %2;"
                 :: "r"(dst), "l"(src), "r"(srcbytes) : "memory");
}
#define CP_COMMIT() asm volatile("cp.async.commit_group;" ::: "memory")
#define CP_WAIT1()  asm volatile("cp.async.wait_group 1;" ::: "memory")
#define CP_WAIT0()  asm volatile("cp.async.wait_group 0;" ::: "memory")

#define MMA_TF32(d, a, b) \
    asm volatile("mma.sync.aligned.m16n8k8.row.col.f32.tf32.tf32.f32 " \
        "{%0,%1,%2,%3},{%4,%5,%6,%7},{%8,%9},{%0,%1,%2,%3};" \
        : "+f"((d)[0]), "+f"((d)[1]), "+f"((d)[2]), "+f"((d)[3]) \
        : "r"((a)[0]), "r"((a)[1]), "r"((a)[2]), "r"((a)[3]), \
          "r"((b)[0]), "r"((b)[1]))

// ASEL: 0=g_xc 1=g_Hbuf 2=g_Sbuf ; BSEL: 0=g_W1c 1=g_W2c 2=g_sW1c 3=g_sW2c
// CSEL: 0=param 1=g_Hbuf 2=g_Ybuf 3=g_Sbuf
template<int ASEL, int BSEL, int CSEL, bool MOE, bool GATHER, bool GELU>
__global__ void __launch_bounds__(256)
gemm_tc(const float* __restrict__ biasB, float* __restrict__ Cp, int Kd, int Nd) {
    extern __shared__ float smf[];
    __shared__ int rtok_s[TILE];

    const float* A = (ASEL == 0) ? g_xc : (ASEL == 1 ? g_Hbuf : g_Sbuf);
    const float* Bw = (BSEL == 0) ? g_W1c : (BSEL == 1 ? g_W2c : (BSEL == 2 ? g_sW1c : g_sW2c));
    float* C = (CSEL == 0) ? Cp : (CSEL == 1 ? g_Hbuf : (CSEL == 2 ? g_Ybuf : g_Sbuf));

    int mt = blockIdx.x, nt = blockIdx.y;
    int row0;
    const float* Bp;
    const float* bp;
    if (MOE) {
        int expert = g_tile_expert[mt];
        if (expert < 0) return;
        row0 = g_tile_row0[mt];
        Bp = Bw + (size_t)expert * Kd * Nd;
        bp = biasB + (size_t)expert * Nd;
    } else {
        row0 = mt * TILE;
        Bp = Bw;
        bp = biasB;
    }
    int n0 = nt * BN;

    int tid = threadIdx.x;
    if (GATHER) {
        if (tid < TILE) rtok_s[tid] = g_row_token[row0 + tid];
        __syncthreads();
    }

    uint32_t sbase = (uint32_t)__cvta_generic_to_shared(smf);

    // ---- stage issue ----
    auto issue = [&](int s, int k0) {
        uint32_t so = sbase + (uint32_t)(s * STAGEW * 4);
        #pragma unroll
        for (int j = 0; j < 4; j++) {            // A: 128 rows x 32k
            int c = tid + j * 256;
            int row = c >> 3, kq = c & 7;
            uint32_t dst = so + (uint32_t)((row * 36 + kq * 4) * 4);
            if (GATHER) {
                int tok = rtok_s[row];
                const float* src = (tok < 0) ? A : A + (size_t)tok * Kd + k0 + kq * 4;
                cpa16(dst, src, tok < 0 ? 0 : 16);
            } else {
                cpa16(dst, A + (size_t)(row0 + row) * Kd + k0 + kq * 4, 16);
            }
        }
        #pragma unroll
        for (int j = 0; j < 8; j++) {            // B: 32k x 256n
            int c = tid + j * 256;
            int k = c >> 6, nq = c & 63;
            uint32_t dst = so + (uint32_t)((AW + k * 264 + nq * 4) * 4);
            cpa16(dst, Bp + (size_t)(k0 + k) * Nd + n0 + nq * 4, 16);
        }
        CP_COMMIT();
    };

    const int lane = tid & 31;
    const int wid = tid >> 5;
    const int warpM = wid & 1;        // 2 warps in M
    const int warpN = wid >> 1;       // 4 warps in N
    const int quad = lane >> 2, qlane = lane & 3;

    float acc[4][8][4];
    #pragma unroll
    for (int mi = 0; mi < 4; mi++)
        #pragma unroll
        for (int ni = 0; ni < 8; ni++)
            #pragma unroll
            for (int r = 0; r < 4; r++) acc[mi][ni][r] = 0.0f;

    const int a_base = (warpM * 64 + quad) * 36 + qlane;
    const int b_base = qlane * 264 + warpN * 64 + quad;

    const int iters = Kd / BKT;
    issue(0, 0);

    for (int it = 0; it < iters; ++it) {
        if (it + 1 < iters) { issue((it + 1) & 1, (it + 1) * BKT); CP_WAIT1(); }
        else                { CP_WAIT0(); }
        __syncthreads();

        const int ao = (it & 1) * STAGEW;
        const int bo = ao + AW;
        #pragma unroll
        for (int ks = 0; ks < 4; ks++) {
            uint32_t a[4][4], b[8][2];
            #pragma unroll
            for (int mi = 0; mi < 4; mi++) {
                int idx = ao + a_base + mi * (16 * 36) + ks * 8;
                a[mi][0] = __float_as_uint(smf[idx]);
                a[mi][1] = __float_as_uint(smf[idx + 8 * 36]);
                a[mi][2] = __float_as_uint(smf[idx + 4]);
                a[mi][3] = __float_as_uint(smf[idx + 8 * 36 + 4]);
            }
            #pragma unroll
            for (int ni = 0; ni < 8; ni++) {
                int idx = bo + b_base + ks * (8 * 264) + ni * 8;
                b[ni][0] = __float_as_uint(smf[idx]);
                b[ni][1] = __float_as_uint(smf[idx + 4 * 264]);
            }
            #pragma unroll
            for (int mi = 0; mi < 4; mi++)
                #pragma unroll
                for (int ni = 0; ni < 8; ni++)
                    MMA_TF32(acc[mi][ni], a[mi], b[ni]);
        }
        __syncthreads();
    }

    // ---- epilogue ----
    #pragma unroll
    for (int mi = 0; mi < 4; mi++) {
        int rg = row0 + warpM * 64 + mi * 16 + quad;
        #pragma unroll
        for (int ni = 0; ni < 8; ni++) {
            int cg = n0 + warpN * 64 + ni * 8 + qlane * 2;
            float bb0 = bp[cg], bb1 = bp[cg + 1];
            float v0 = acc[mi][ni][0] + bb0;
            float v1 = acc[mi][ni][1] + bb1;
            float v2 = acc[mi][ni][2] + bb0;
            float v3 = acc[mi][ni][3] + bb1;
            if (GELU) {
                v0 = gelu_exact(v0); v1 = gelu_exact(v1);
                v2 = gelu_exact(v2); v3 = gelu_exact(v3);
            }
            if (CSEL == 1 || CSEL == 3) { // feeds next tf32 GEMM: rna-round now
                v0 = tf32_rna(v0); v1 = tf32_rna(v1);
                v2 = tf32_rna(v2); v3 = tf32_rna(v3);
            }
            *(float2*)&C[(size_t)rg * Nd + cg]       = make_float2(v0, v1);
            *(float2*)&C[(size_t)(rg + 8) * Nd + cg] = make_float2(v2, v3);
        }
    }
}

// ---------------- combine ----------------
__global__ void combine_kernel(float* __restrict__ out) {
    int t = blockIdx.x;
    int d = threadIdx.x * 4;
    float4 o = *(float4*)&out[(size_t)t * DD + d];
    #pragma unroll
    for (int k = 0; k < KK; k++) {
        int p = g_pos_of[t*KK + k];
        float w = g_gate_w[t*KK + k];
        float4 y = *(const float4*)&g_Ybuf[(size_t)p * DD + d];
        o.x += w * y.x; o.y += w * y.y; o.z += w * y.z; o.w += w * y.w;
    }
    *(float4*)&out[(size_t)t * DD + d] = o;
}

// ---------------- aux loss + counts ----------------
__global__ void finalize_kernel(float* __restrict__ extra, int write_counts) {
    if (threadIdx.x == 0) {
        float a = 0.0f;
        for (int e = 0; e < EE; e++) {
            float P = g_Psum[e] / (float)TT;
            float F = (float)EE * (float)g_counts[e] / (float)(KK * TT);
            a += P * F;
        }
        extra[0] = a;
    }
    if (write_counts && threadIdx.x < EE)
        extra[1 + threadIdx.x] = (float)g_counts[threadIdx.x];
}

extern "C" void kernel_launch(void* const* d_in, const int* in_sizes, int n_in,
                              void* d_out, int out_size) {
    const float* x    = (const float*)d_in[0];
    const float* gW   = (const float*)d_in[1];
    const float* gb   = (const float*)d_in[2];
    const float* bias = (const float*)d_in[3];
    const float* W1   = (const float*)d_in[4];
    const float* b1   = (const float*)d_in[5];
    const float* W2   = (const float*)d_in[6];
    const float* b2   = (const float*)d_in[7];
    const float* sW1  = (const float*)d_in[8];
    const float* sb1  = (const float*)d_in[9];
    const float* sW2  = (const float*)d_in[10];
    const float* sb2  = (const float*)d_in[11];
    float* out = (float*)d_out;

    // raise dynamic smem limit on all GEMM instantiations (idempotent)
    cudaFuncSetAttribute(gemm_tc<0,0,1,true,true,true>,   cudaFuncAttributeMaxDynamicSharedMemorySize, SMEM_BYTES);
    cudaFuncSetAttribute(gemm_tc<1,1,2,true,false,false>, cudaFuncAttributeMaxDynamicSharedMemorySize, SMEM_BYTES);
    cudaFuncSetAttribute(gemm_tc<0,2,3,false,false,true>, cudaFuncAttributeMaxDynamicSharedMemorySize, SMEM_BYTES);
    cudaFuncSetAttribute(gemm_tc<2,3,0,false,false,false>,cudaFuncAttributeMaxDynamicSharedMemorySize, SMEM_BYTES);

    init_kernel<<<(ROWS_MAX + 255) / 256, 256>>>();
    gate_kernel<<<TT, 256>>>(x, gW, gb, bias);
    scan_kernel<<<1, 32>>>();
    scatter_kernel<<<(TT + 255) / 256, 256>>>();

    // tf32(rna) conversions
    float* xc;  cudaGetSymbolAddress((void**)&xc,  g_xc);
    float* w1c; cudaGetSymbolAddress((void**)&w1c, g_W1c);
    float* w2c; cudaGetSymbolAddress((void**)&w2c, g_W2c);
    float* s1c; cudaGetSymbolAddress((void**)&s1c, g_sW1c);
    float* s2c; cudaGetSymbolAddress((void**)&s2c, g_sW2c);
    convert_kernel<<<(TT*DD/4 + 255)/256, 256>>>((const float4*)x,   (float4*)xc,  TT*DD/4);
    convert_kernel<<<(EE*DD*HH/4 + 255)/256, 256>>>((const float4*)W1,(float4*)w1c, EE*DD*HH/4);
    convert_kernel<<<(EE*HH*DD/4 + 255)/256, 256>>>((const float4*)W2,(float4*)w2c, EE*HH*DD/4);
    convert_kernel<<<(DD*HH/4 + 255)/256, 256>>>((const float4*)sW1, (float4*)s1c, DD*HH/4);
    convert_kernel<<<(HH*DD/4 + 255)/256, 256>>>((const float4*)sW2, (float4*)s2c, HH*DD/4);

    // expert GEMM1: Hbuf = tf32(gelu(gather(xc) @ W1_e + b1_e))   [rows x 768]
    gemm_tc<0,0,1,true,true,true><<<dim3(MTILES_MAX, HH/BN), 256, SMEM_BYTES>>>(b1, nullptr, DD, HH);
    // expert GEMM2: Ybuf = Hbuf @ W2_e + b2_e                     [rows x 1024]
    gemm_tc<1,1,2,true,false,false><<<dim3(MTILES_MAX, DD/BN), 256, SMEM_BYTES>>>(b2, nullptr, HH, DD);
    // shared GEMM1: Sbuf = tf32(gelu(xc @ sW1 + sb1))             [4096 x 768]
    gemm_tc<0,2,3,false,false,true><<<dim3(TT/TILE, HH/BN), 256, SMEM_BYTES>>>(sb1, nullptr, DD, HH);
    // shared GEMM2: out = Sbuf @ sW2 + sb2                        [4096 x 1024]
    gemm_tc<2,3,0,false,false,false><<<dim3(TT/TILE, DD/BN), 256, SMEM_BYTES>>>(sb2, out, HH, DD);

    combine_kernel<<<TT, 256>>>(out);

    if (out_size > OUT_MAIN) {
        int write_counts = (out_size >= OUT_MAIN + 1 + EE) ? 1 : 0;
        finalize_kernel<<<1, 32>>>(out + OUT_MAIN, write_counts);
    }
}